// round 8
// baseline (speedup 1.0000x reference)
#include <cuda_runtime.h>

// ---------------------------------------------------------------------------
// IMEX-ETD: CG-solve (I - DT*D*Lap_neumann) x = u, then pointwise ETD update.
// Round 8: direct dot products in the fused pass (RR honest -> stable 3-step
// trajectory; only beta^2-damped terms recursive), TY=2 row-pairing to cut
// memory instructions per element (~27%), TBLK=768 for register headroom.
// u_tilde reconstructed in epilogue from saved r generations.
// ---------------------------------------------------------------------------

#define N_ELEM   8388608     // 8 * 1 * 1024 * 1024
#define N4       2097152     // float4 count
#define M2       1048576     // row-pair work items (N4 / 2)
#define ROW4     256         // float4s per row
#define GBLK     152
#define TBLK     768
#define NWARP    24
#define NTHREADS (GBLK * TBLK)

#define DT_C     0.1f
#define CG_TAU   0.015
#define NGEN     6

__device__ float g_rg[NGEN][N_ELEM];   // r generations
__device__ float g_s0[N_ELEM];         // Ap ping
__device__ float g_s1[N_ELEM];         // Ap pong

__device__ double g_pd[2][5][GBLK];    // pass dot partials (parity x {RR,RW,WW,WS,RS})
__device__ double g_pi[3][GBLK];       // init partials: rs, pAp, sAs

__device__ unsigned g_cnt = 0;
__device__ volatile unsigned g_gen = 0;

// ---------------------------------------------------------------------------

__device__ __forceinline__ void grid_bar() {
    __syncthreads();
    __threadfence();                       // release
    if (threadIdx.x == 0) {
        unsigned snap = g_gen;
        unsigned arrived = atomicAdd(&g_cnt, 1u);
        if (arrived == GBLK - 1) {
            g_cnt = 0;
            __threadfence();
            g_gen = snap + 1u;
        } else {
            while (g_gen == snap) { }
        }
    }
    __syncthreads();
    __threadfence();                       // acquire (CCTL.IVALL): L1 coherent
}

__device__ __forceinline__ double block_reduce_d(double v) {
    __shared__ double sh[32];
    int lane = threadIdx.x & 31;
    int w    = threadIdx.x >> 5;
#pragma unroll
    for (int o = 16; o; o >>= 1) v += __shfl_down_sync(0xffffffffu, v, o);
    if (lane == 0) sh[w] = v;
    __syncthreads();
    if (w == 0) {
        v = (lane < NWARP) ? sh[lane] : 0.0;
#pragma unroll
        for (int o = 16; o; o >>= 1) v += __shfl_down_sync(0xffffffffu, v, o);
    }
    return v;
}

__device__ __forceinline__ double sum_partials_d(const double* a) {
    __shared__ double tot;
    int t = threadIdx.x;
    if (t < 32) {
        double s = 0.0;
#pragma unroll
        for (int j = t; j < GBLK; j += 32) s += a[j];
#pragma unroll
        for (int o = 16; o; o >>= 1) s += __shfl_down_sync(0xffffffffu, s, o);
        if (t == 0) tot = s;
    }
    __syncthreads();
    return tot;
}

// ---------------------------------------------------------------------------

__device__ __forceinline__ float dot4f(float4 a, float4 b) {
    return fmaf(a.x, b.x, fmaf(a.y, b.y, fmaf(a.z, b.z, a.w * b.w)));
}

__device__ __forceinline__ float4 lap_mk(float4 c, float4 t, float4 b,
                                         float lf, float rt) {
    float4 L;
    L.x = fmaf(-4.0f, c.x, (lf  + c.y) + (t.x + b.x));
    L.y = fmaf(-4.0f, c.y, (c.x + c.z) + (t.y + b.y));
    L.z = fmaf(-4.0f, c.z, (c.y + c.w) + (t.z + b.z));
    L.w = fmaf(-4.0f, c.w, (c.z + rt ) + (t.w + b.w));
    return L;
}

// work-item decomposition: m -> (plane, row-pair, x4)
__device__ __forceinline__ void decode2(int m, int& j0, bool& hT, bool& hB,
                                        bool& hL, bool& hR) {
    int x4 = m & 255;
    int yp = (m >> 8) & 511;
    int pl = m >> 17;
    int ya = yp << 1;
    j0 = (pl << 18) + (ya << 8) + x4;   // plane stride 2^18 float4s
    hT = (ya > 0);
    hB = (ya < 1022);                   // row b = ya+1 has bottom iff ya+1 < 1023
    hL = (x4 > 0);
    hR = (x4 < 255);
}

// ---------------------------------------------------------------------------

__global__ void __launch_bounds__(TBLK, 1)
imexetd_cg_kernel(const float* __restrict__ u,
                  const float* __restrict__ D,
                  const float* __restrict__ kp,
                  const float* __restrict__ aCp,
                  const float* __restrict__ Ctp,
                  float* __restrict__ out)
{
    const int tid = blockIdx.x * TBLK + threadIdx.x;
    const float4* __restrict__ D4 = (const float4*)D;
    const float*  __restrict__ Df = D;

    // ================= init pass A: r0 = DT*D*lap(u), TY=2 =================
    {
        const float4* __restrict__ u4 = (const float4*)u;
        const float*  __restrict__ uf = u;
        float4* __restrict__ r4w = (float4*)g_rg[0];
        for (int m = tid; m < M2; m += NTHREADS) {
            int j0; bool hT, hB, hL, hR;
            decode2(m, j0, hT, hB, hL, hR);
            int j1 = j0 + ROW4;

            float4 uA = __ldg(u4 + j0);
            float4 uB = __ldg(u4 + j1);
            float4 uT = hT ? __ldg(u4 + (j0 - ROW4)) : uA;
            float4 uD = hB ? __ldg(u4 + (j1 + ROW4)) : uB;
            float uLa = hL ? __ldg(uf + 4*j0 - 1) : uA.x;
            float uRa = hR ? __ldg(uf + 4*j0 + 4) : uA.w;
            float uLb = hL ? __ldg(uf + 4*j1 - 1) : uB.x;
            float uRb = hR ? __ldg(uf + 4*j1 + 4) : uB.w;
            float4 dA = __ldg(D4 + j0);
            float4 dB = __ldg(D4 + j1);

            float4 la = lap_mk(uA, uT, uB, uLa, uRa);
            float4 lb = lap_mk(uB, uA, uD, uLb, uRb);
            float4 ra, rb;
            ra.x = DT_C * dA.x * la.x;  ra.y = DT_C * dA.y * la.y;
            ra.z = DT_C * dA.z * la.z;  ra.w = DT_C * dA.w * la.w;
            rb.x = DT_C * dB.x * lb.x;  rb.y = DT_C * dB.y * lb.y;
            rb.z = DT_C * dB.z * lb.z;  rb.w = DT_C * dB.w * lb.w;
            r4w[j0] = ra;
            r4w[j1] = rb;
        }
    }
    grid_bar();

    // ============ init pass B: s0 = r0 - DT*D*lap(r0); dots, TY=2 ==========
    {
        const float4* __restrict__ r4 = (const float4*)g_rg[0];
        const float*  __restrict__ rf = (const float*)g_rg[0];
        float4* __restrict__ s4w = (float4*)g_s0;
        double ars = 0.0, apa = 0.0, asa = 0.0;
        for (int m = tid; m < M2; m += NTHREADS) {
            int j0; bool hT, hB, hL, hR;
            decode2(m, j0, hT, hB, hL, hR);
            int j1 = j0 + ROW4;

            float4 rA = r4[j0];
            float4 rB = r4[j1];
            float4 rT = hT ? r4[j0 - ROW4] : rA;
            float4 rD = hB ? r4[j1 + ROW4] : rB;
            float rLa = hL ? rf[4*j0 - 1] : rA.x;
            float rRa = hR ? rf[4*j0 + 4] : rA.w;
            float rLb = hL ? rf[4*j1 - 1] : rB.x;
            float rRb = hR ? rf[4*j1 + 4] : rB.w;
            float4 dA = __ldg(D4 + j0);
            float4 dB = __ldg(D4 + j1);

            float4 la = lap_mk(rA, rT, rB, rLa, rRa);
            float4 lb = lap_mk(rB, rA, rD, rLb, rRb);
            float4 sa, sb;
            sa.x = fmaf(-DT_C * dA.x, la.x, rA.x);
            sa.y = fmaf(-DT_C * dA.y, la.y, rA.y);
            sa.z = fmaf(-DT_C * dA.z, la.z, rA.z);
            sa.w = fmaf(-DT_C * dA.w, la.w, rA.w);
            sb.x = fmaf(-DT_C * dB.x, lb.x, rB.x);
            sb.y = fmaf(-DT_C * dB.y, lb.y, rB.y);
            sb.z = fmaf(-DT_C * dB.z, lb.z, rB.z);
            sb.w = fmaf(-DT_C * dB.w, lb.w, rB.w);
            s4w[j0] = sa;
            s4w[j1] = sb;

            ars += (double)(dot4f(rA, rA) + dot4f(rB, rB));
            apa += (double)(dot4f(rA, sa) + dot4f(rB, sb));
            asa += (double)(dot4f(sa, sa) + dot4f(sb, sb));
        }
        double v;
        v = block_reduce_d(ars);
        if (threadIdx.x == 0) g_pi[0][blockIdx.x] = v;
        __syncthreads();
        v = block_reduce_d(apa);
        if (threadIdx.x == 0) g_pi[1][blockIdx.x] = v;
        __syncthreads();
        v = block_reduce_d(asa);
        if (threadIdx.x == 0) g_pi[2][blockIdx.x] = v;
    }
    grid_bar();
    double rs  = sum_partials_d(g_pi[0]);
    double pAp = sum_partials_d(g_pi[1]);
    double sAs = sum_partials_d(g_pi[2]);

    // =========================== CG alpha-steps ============================
    float alph[NGEN];
    float bet [NGEN];
    int it = 0;
    int npass = 0;
    int scur = 0;

    for (;;) {
        float alpha_f = (float)(rs / (pAp + 1e-300));
        double ad = (double)alpha_f;
        double rs_pred = rs - 2.0 * ad * pAp + ad * ad * sAs;
        if (rs_pred < 0.0) rs_pred = 0.0;
        alph[it] = alpha_f;
        it++;
        if (sqrt(rs_pred) < CG_TAU || it >= NGEN) break;   // final a*p in epilogue

        float beta_f = (float)(rs_pred / (rs + 1e-300));
        bet[it] = beta_f;

        const float4* __restrict__ rsrc4 = (const float4*)g_rg[npass];
        const float*  __restrict__ rs_f  = (const float*)g_rg[npass];
        const float4* __restrict__ ssrc4 = (const float4*)(scur ? g_s1 : g_s0);
        const float*  __restrict__ ss_f  = (const float*)(scur ? g_s1 : g_s0);
        float4* __restrict__ rdst4 = (float4*)g_rg[npass + 1];
        float4* __restrict__ sdst4 = (float4*)(scur ? g_s0 : g_s1);

        double aRR = 0.0, aRW = 0.0, aWW = 0.0, aWS = 0.0, aRS = 0.0;

        for (int m = tid; m < M2; m += NTHREADS) {
            int j0; bool hT, hB, hL, hR;
            decode2(m, j0, hT, hB, hL, hR);
            int j1 = j0 + ROW4;

            // windows (plain loads: post-acquire coherent)
            float4 rA = rsrc4[j0];
            float4 rB = rsrc4[j1];
            float4 rT = hT ? rsrc4[j0 - ROW4] : rA;
            float4 rD = hB ? rsrc4[j1 + ROW4] : rB;
            float4 sA = ssrc4[j0];
            float4 sB = ssrc4[j1];
            float4 sT = hT ? ssrc4[j0 - ROW4] : sA;
            float4 sD = hB ? ssrc4[j1 + ROW4] : sB;
            float rLa = hL ? rs_f[4*j0 - 1] : rA.x;
            float rRa = hR ? rs_f[4*j0 + 4] : rA.w;
            float rLb = hL ? rs_f[4*j1 - 1] : rB.x;
            float rRb = hR ? rs_f[4*j1 + 4] : rB.w;
            float sLa = hL ? ss_f[4*j0 - 1] : sA.x;
            float sRa = hR ? ss_f[4*j0 + 4] : sA.w;
            float sLb = hL ? ss_f[4*j1 - 1] : sB.x;
            float sRb = hR ? ss_f[4*j1 + 4] : sB.w;
            float4 dA = __ldg(D4 + j0);
            float4 dB = __ldg(D4 + j1);

            // --- row a ---
            {
                float4 lr = lap_mk(rA, rT, rB, rLa, rRa);
                float4 ls = lap_mk(sA, sT, sB, sLa, sRa);
                float4 rn, w, sn;
                rn.x = fmaf(-alpha_f, sA.x, rA.x);
                rn.y = fmaf(-alpha_f, sA.y, rA.y);
                rn.z = fmaf(-alpha_f, sA.z, rA.z);
                rn.w = fmaf(-alpha_f, sA.w, rA.w);
                float lx = fmaf(-alpha_f, ls.x, lr.x);
                float ly = fmaf(-alpha_f, ls.y, lr.y);
                float lz = fmaf(-alpha_f, ls.z, lr.z);
                float lw = fmaf(-alpha_f, ls.w, lr.w);
                w.x = fmaf(-DT_C * dA.x, lx, rn.x);
                w.y = fmaf(-DT_C * dA.y, ly, rn.y);
                w.z = fmaf(-DT_C * dA.z, lz, rn.z);
                w.w = fmaf(-DT_C * dA.w, lw, rn.w);
                sn.x = fmaf(beta_f, sA.x, w.x);
                sn.y = fmaf(beta_f, sA.y, w.y);
                sn.z = fmaf(beta_f, sA.z, w.z);
                sn.w = fmaf(beta_f, sA.w, w.w);
                rdst4[j0] = rn;
                sdst4[j0] = sn;
                aRR += (double)dot4f(rn, rn);
                aRW += (double)dot4f(rn, w);
                aWW += (double)dot4f(w,  w);
                aWS += (double)dot4f(w,  sA);
                aRS += (double)dot4f(rn, sA);
            }
            // --- row b ---
            {
                float4 lr = lap_mk(rB, rA, rD, rLb, rRb);
                float4 ls = lap_mk(sB, sA, sD, sLb, sRb);
                float4 rn, w, sn;
                rn.x = fmaf(-alpha_f, sB.x, rB.x);
                rn.y = fmaf(-alpha_f, sB.y, rB.y);
                rn.z = fmaf(-alpha_f, sB.z, rB.z);
                rn.w = fmaf(-alpha_f, sB.w, rB.w);
                float lx = fmaf(-alpha_f, ls.x, lr.x);
                float ly = fmaf(-alpha_f, ls.y, lr.y);
                float lz = fmaf(-alpha_f, ls.z, lr.z);
                float lw = fmaf(-alpha_f, ls.w, lr.w);
                w.x = fmaf(-DT_C * dB.x, lx, rn.x);
                w.y = fmaf(-DT_C * dB.y, ly, rn.y);
                w.z = fmaf(-DT_C * dB.z, lz, rn.z);
                w.w = fmaf(-DT_C * dB.w, lw, rn.w);
                sn.x = fmaf(beta_f, sB.x, w.x);
                sn.y = fmaf(beta_f, sB.y, w.y);
                sn.z = fmaf(beta_f, sB.z, w.z);
                sn.w = fmaf(beta_f, sB.w, w.w);
                rdst4[j1] = rn;
                sdst4[j1] = sn;
                aRR += (double)dot4f(rn, rn);
                aRW += (double)dot4f(rn, w);
                aWW += (double)dot4f(w,  w);
                aWS += (double)dot4f(w,  sB);
                aRS += (double)dot4f(rn, sB);
            }
        }

        int par = (npass + 1) & 1;
        {
            double v;
            v = block_reduce_d(aRR);
            if (threadIdx.x == 0) g_pd[par][0][blockIdx.x] = v;
            __syncthreads();
            v = block_reduce_d(aRW);
            if (threadIdx.x == 0) g_pd[par][1][blockIdx.x] = v;
            __syncthreads();
            v = block_reduce_d(aWW);
            if (threadIdx.x == 0) g_pd[par][2][blockIdx.x] = v;
            __syncthreads();
            v = block_reduce_d(aWS);
            if (threadIdx.x == 0) g_pd[par][3][blockIdx.x] = v;
            __syncthreads();
            v = block_reduce_d(aRS);
            if (threadIdx.x == 0) g_pd[par][4][blockIdx.x] = v;
        }
        grid_bar();
        double RR = sum_partials_d(g_pd[par][0]);
        double RW = sum_partials_d(g_pd[par][1]);
        double WW = sum_partials_d(g_pd[par][2]);
        double WS = sum_partials_d(g_pd[par][3]);
        double RS = sum_partials_d(g_pd[par][4]);

        double bd = (double)beta_f;
        rs  = RR;                                   // direct, honest
        pAp = RW + 2.0 * bd * RS + bd * bd * pAp;   // beta^2 term damped
        sAs = WW + 2.0 * bd * WS + bd * bd * sAs;
        npass++;
        scur ^= 1;
    }

    // ---- coefficients: u_tilde = u + sum_{m<it} c_m * r_m ----
    float c[NGEN];
    c[it - 1] = alph[it - 1];
    for (int m = it - 2; m >= 0; m--)
        c[m] = fmaf(bet[m + 1], c[m + 1], alph[m]);

    // ========================= ETD epilogue ================================
    float kk = __ldg(&kp[0]);
    float a  = kk - __ldg(&aCp[0]) * __ldg(&Ctp[0]);
    float bc = kk;                               // k / K_CAP, K_CAP = 1
    float adc = fminf(fmaxf(a * DT_C, -60.0f), 60.0f);
    float e   = expf(adc);
    float em1 = e - 1.0f;

    const float4* __restrict__ u4 = (const float4*)u;
    float4* __restrict__ o4 = (float4*)out;
    const int g = it;

    for (int j = tid; j < N4; j += NTHREADS) {
        float4 ut = __ldg(u4 + j);
        for (int m = 0; m < g; m++) {
            float4 rv = ((const float4*)g_rg[m])[j];
            float cm = c[m];
            ut.x = fmaf(cm, rv.x, ut.x);
            ut.y = fmaf(cm, rv.y, ut.y);
            ut.z = fmaf(cm, rv.z, ut.z);
            ut.w = fmaf(cm, rv.w, ut.w);
        }
        float4 un;
        {
            float num = a * ut.x * e;
            float den = fmaf(bc * ut.x, em1, a);
            un.x = (fabsf(den) > 1e-12f) ? (num / den) : ut.x;
            num = a * ut.y * e;
            den = fmaf(bc * ut.y, em1, a);
            un.y = (fabsf(den) > 1e-12f) ? (num / den) : ut.y;
            num = a * ut.z * e;
            den = fmaf(bc * ut.z, em1, a);
            un.z = (fabsf(den) > 1e-12f) ? (num / den) : ut.z;
            num = a * ut.w * e;
            den = fmaf(bc * ut.w, em1, a);
            un.w = (fabsf(den) > 1e-12f) ? (num / den) : ut.w;
        }
        un.x = fminf(fmaxf(un.x, 0.0f), 1.0f);
        un.y = fminf(fmaxf(un.y, 0.0f), 1.0f);
        un.z = fminf(fmaxf(un.z, 0.0f), 1.0f);
        un.w = fminf(fmaxf(un.w, 0.0f), 1.0f);
        o4[j] = un;
    }
}

// ---------------------------------------------------------------------------

extern "C" void kernel_launch(void* const* d_in, const int* in_sizes, int n_in,
                              void* d_out, int out_size)
{
    const float* u   = (const float*)d_in[0];
    const float* D   = (const float*)d_in[1];
    const float* k   = (const float*)d_in[2];
    const float* aC  = (const float*)d_in[3];
    const float* C_t = (const float*)d_in[4];
    float* out = (float*)d_out;

    imexetd_cg_kernel<<<GBLK, TBLK>>>(u, D, k, aC, C_t, out);
}

// round 9
// speedup vs baseline: 2.0000x; 2.0000x over previous
#include <cuda_runtime.h>

// ---------------------------------------------------------------------------
// IMEX-ETD: CG-solve (I - DT*D*Lap_neumann) x = u, then pointwise ETD update.
// Round 9: round-6 skeleton (direct pAp/sAs dots each pass -> exact 3-step
// trajectory) + two wins:
//   (a) dl stream dropped: u_tilde = u + sum c_m r_m from saved r generations
//   (b) lateral stencil neighbors via warp shuffle (edge lanes only hit gmem)
// Pass traffic 7N (was 9N), fewer memory instructions everywhere.
// ---------------------------------------------------------------------------

#define N_ELEM   8388608     // 8 * 1 * 1024 * 1024
#define N4       2097152     // float4 count
#define ROW4     256         // float4s per row
#define GBLK     152
#define TBLK     1024
#define NTHREADS (GBLK * TBLK)

#define DT_C     0.1f
#define CG_TAU   0.015
#define NGEN     5

__device__ float g_rg[NGEN][N_ELEM];   // r generations (r0..r4)
__device__ float g_s0[N_ELEM];          // Ap ping
__device__ float g_s1[N_ELEM];          // Ap pong
__device__ float g_p [N_ELEM];

__device__ double g_pd[2][2][GBLK];     // pass partials (parity x {pAp,sAs})
__device__ double g_pi[3][GBLK];        // init partials: rs, pAp, sAs

__device__ unsigned g_cnt = 0;
__device__ volatile unsigned g_gen = 0;

// ---------------------------------------------------------------------------

__device__ __forceinline__ void grid_bar() {
    __syncthreads();
    __threadfence();                       // release
    if (threadIdx.x == 0) {
        unsigned snap = g_gen;
        unsigned arrived = atomicAdd(&g_cnt, 1u);
        if (arrived == GBLK - 1) {
            g_cnt = 0;
            __threadfence();
            g_gen = snap + 1u;
        } else {
            while (g_gen == snap) { }
        }
    }
    __syncthreads();
    __threadfence();                       // acquire (CCTL.IVALL): L1 coherent
}

__device__ __forceinline__ double block_reduce_d(double v) {
    __shared__ double sh[32];
    int lane = threadIdx.x & 31;
    int w    = threadIdx.x >> 5;
#pragma unroll
    for (int o = 16; o; o >>= 1) v += __shfl_down_sync(0xffffffffu, v, o);
    if (lane == 0) sh[w] = v;
    __syncthreads();
    if (w == 0) {
        v = sh[lane];
#pragma unroll
        for (int o = 16; o; o >>= 1) v += __shfl_down_sync(0xffffffffu, v, o);
    }
    return v;
}

__device__ __forceinline__ double sum_partials_d(const double* a) {
    __shared__ double tot;
    int t = threadIdx.x;
    if (t < 32) {
        double s = 0.0;
#pragma unroll
        for (int j = t; j < GBLK; j += 32) s += a[j];
#pragma unroll
        for (int o = 16; o; o >>= 1) s += __shfl_down_sync(0xffffffffu, s, o);
        if (t == 0) tot = s;
    }
    __syncthreads();
    return tot;
}

// ---------------------------------------------------------------------------

__device__ __forceinline__ float dot4f(float4 a, float4 b) {
    return fmaf(a.x, b.x, fmaf(a.y, b.y, fmaf(a.z, b.z, a.w * b.w)));
}

__device__ __forceinline__ float4 lap_mk(float4 c, float4 t, float4 b,
                                         float lf, float rt) {
    float4 L;
    L.x = fmaf(-4.0f, c.x, (lf  + c.y) + (t.x + b.x));
    L.y = fmaf(-4.0f, c.y, (c.x + c.z) + (t.y + b.y));
    L.z = fmaf(-4.0f, c.z, (c.y + c.w) + (t.z + b.z));
    L.w = fmaf(-4.0f, c.w, (c.z + rt ) + (t.w + b.w));
    return L;
}

// r0 = DT * D * lap(u) at float4 index j
__device__ __forceinline__ float4 r0_vec(const float* __restrict__ u,
                                         const float* __restrict__ D, int j) {
    int x4 = j & (ROW4 - 1);
    int y  = (j >> 8) & 1023;
    const float4* u4 = (const float4*)u;
    float4 c = __ldg(u4 + j);
    float4 t = (y > 0)    ? __ldg(u4 + (j - ROW4)) : c;
    float4 b = (y < 1023) ? __ldg(u4 + (j + ROW4)) : c;
    float lf = (x4 > 0)        ? __ldg(u + 4*j - 1) : c.x;
    float rt = (x4 < ROW4 - 1) ? __ldg(u + 4*j + 4) : c.w;
    float4 dd = __ldg(((const float4*)D) + j);
    float4 lp = lap_mk(c, t, b, lf, rt);
    float4 rv;
    rv.x = DT_C * dd.x * lp.x;
    rv.y = DT_C * dd.y * lp.y;
    rv.z = DT_C * dd.z * lp.z;
    rv.w = DT_C * dd.w * lp.w;
    return rv;
}

__device__ __forceinline__ float r0_scalar(const float* __restrict__ u,
                                           const float* __restrict__ D, int i) {
    int x = i & 1023;
    int y = (i >> 10) & 1023;
    float c = __ldg(&u[i]);
    float l = (x > 0)    ? __ldg(&u[i - 1])    : c;
    float r = (x < 1023) ? __ldg(&u[i + 1])    : c;
    float t = (y > 0)    ? __ldg(&u[i - 1024]) : c;
    float b = (y < 1023) ? __ldg(&u[i + 1024]) : c;
    return DT_C * __ldg(&D[i]) * fmaf(-4.0f, c, (l + r) + (t + b));
}

// ---------------------------------------------------------------------------
// Fused CG pass, 7N traffic. Lateral neighbors via warp shuffle (the loop is
// warp-uniform: N4 and NTHREADS are multiples of 32, each warp covers 32
// contiguous float4s of one row). Dots (pn,sn), (sn,sn) measured DIRECTLY.
// FIRST: p aliases rsrc (p0 = r0).

template <bool FIRST>
__device__ __forceinline__ void fused_pass(
    const float4* __restrict__ rsrc4,
    const float4* __restrict__ ssrc4,
    float4*       __restrict__ rdst4,
    float4*       __restrict__ sdst4,
    float4*       __restrict__ p4,
    const float4* __restrict__ D4,
    float alpha_f, float beta_f,
    int tid, int lane, double& apa_out, double& asa_out)
{
    const float* __restrict__ rs_f = (const float*)rsrc4;
    const float* __restrict__ ss_f = (const float*)ssrc4;
    double apa = 0.0, asa = 0.0;

    for (int j = tid; j < N4; j += NTHREADS) {
        int x4 = j & (ROW4 - 1);
        int y  = (j >> 8) & 1023;
        bool hT = (y > 0), hB = (y < 1023);

        float4 rc = rsrc4[j];
        float4 sc = ssrc4[j];
        float4 rT = hT ? rsrc4[j - ROW4] : rc;
        float4 rB = hB ? rsrc4[j + ROW4] : rc;
        float4 sT = hT ? ssrc4[j - ROW4] : sc;
        float4 sB = hB ? ssrc4[j + ROW4] : sc;

        // lateral neighbors: shuffle from adjacent lanes; edges hit gmem
        float rL = __shfl_up_sync(0xffffffffu, rc.w, 1);
        float sL = __shfl_up_sync(0xffffffffu, sc.w, 1);
        float rR = __shfl_down_sync(0xffffffffu, rc.x, 1);
        float sR = __shfl_down_sync(0xffffffffu, sc.x, 1);
        if (lane == 0) {
            rL = (x4 > 0) ? rs_f[4*j - 1] : rc.x;
            sL = (x4 > 0) ? ss_f[4*j - 1] : sc.x;
        }
        if (lane == 31) {
            rR = (x4 < ROW4 - 1) ? rs_f[4*j + 4] : rc.w;
            sR = (x4 < ROW4 - 1) ? ss_f[4*j + 4] : sc.w;
        }

        float4 dd = __ldg(D4 + j);
        float4 pv = FIRST ? rc : p4[j];

        float4 lr = lap_mk(rc, rT, rB, rL, rR);
        float4 ls = lap_mk(sc, sT, sB, sL, sR);

        // r_new = r - a*s
        float4 rn;
        rn.x = fmaf(-alpha_f, sc.x, rc.x);
        rn.y = fmaf(-alpha_f, sc.y, rc.y);
        rn.z = fmaf(-alpha_f, sc.z, rc.z);
        rn.w = fmaf(-alpha_f, sc.w, rc.w);

        // w = A r_new = r_new - DT*D*(lap r - a*lap s)
        float4 w;
        {
            float lx = fmaf(-alpha_f, ls.x, lr.x);
            float ly = fmaf(-alpha_f, ls.y, lr.y);
            float lz = fmaf(-alpha_f, ls.z, lr.z);
            float lw = fmaf(-alpha_f, ls.w, lr.w);
            w.x = fmaf(-DT_C * dd.x, lx, rn.x);
            w.y = fmaf(-DT_C * dd.y, ly, rn.y);
            w.z = fmaf(-DT_C * dd.z, lz, rn.z);
            w.w = fmaf(-DT_C * dd.w, lw, rn.w);
        }

        // p_new = r_new + b*p ; s_new = w + b*s
        float4 pn, sn;
        pn.x = fmaf(beta_f, pv.x, rn.x);
        pn.y = fmaf(beta_f, pv.y, rn.y);
        pn.z = fmaf(beta_f, pv.z, rn.z);
        pn.w = fmaf(beta_f, pv.w, rn.w);
        sn.x = fmaf(beta_f, sc.x, w.x);
        sn.y = fmaf(beta_f, sc.y, w.y);
        sn.z = fmaf(beta_f, sc.z, w.z);
        sn.w = fmaf(beta_f, sc.w, w.w);

        rdst4[j] = rn;
        sdst4[j] = sn;
        p4[j]    = pn;

        apa += (double)dot4f(pn, sn);   // direct (valid for non-symmetric A)
        asa += (double)dot4f(sn, sn);
    }
    apa_out = apa;
    asa_out = asa;
}

// ---------------------------------------------------------------------------

__global__ void __launch_bounds__(TBLK, 1)
imexetd_cg_kernel(const float* __restrict__ u,
                  const float* __restrict__ D,
                  const float* __restrict__ kp,
                  const float* __restrict__ aCp,
                  const float* __restrict__ Ctp,
                  float* __restrict__ out)
{
    const int tid  = blockIdx.x * TBLK + threadIdx.x;
    const int lane = threadIdx.x & 31;
    const float4* D4 = (const float4*)D;
    float4* p4 = (float4*)g_p;

    // ---- fused init: r0 = DT*D*lap(u); s0 = A r0 (composed 2-hop stencil,
    //      laterals of r0 via warp shuffle); dots rs, pAp, sAs ----
    {
        float4* __restrict__ r4w = (float4*)g_rg[0];
        float4* __restrict__ s4w = (float4*)g_s0;
        double ars = 0.0, apa = 0.0, asa = 0.0;
        for (int j = tid; j < N4; j += NTHREADS) {
            int x4 = j & (ROW4 - 1);
            int y  = (j >> 8) & 1023;
            float4 rc = r0_vec(u, D, j);
            float4 rT = (y > 0)    ? r0_vec(u, D, j - ROW4) : rc;
            float4 rB = (y < 1023) ? r0_vec(u, D, j + ROW4) : rc;
            float rL = __shfl_up_sync(0xffffffffu, rc.w, 1);
            float rR = __shfl_down_sync(0xffffffffu, rc.x, 1);
            if (lane == 0)
                rL = (x4 > 0) ? r0_scalar(u, D, 4*j - 1) : rc.x;
            if (lane == 31)
                rR = (x4 < ROW4 - 1) ? r0_scalar(u, D, 4*j + 4) : rc.w;
            float4 dd = __ldg(D4 + j);
            float4 lp = lap_mk(rc, rT, rB, rL, rR);
            float4 Av;
            Av.x = fmaf(-DT_C * dd.x, lp.x, rc.x);
            Av.y = fmaf(-DT_C * dd.y, lp.y, rc.y);
            Av.z = fmaf(-DT_C * dd.z, lp.z, rc.z);
            Av.w = fmaf(-DT_C * dd.w, lp.w, rc.w);
            r4w[j] = rc;
            s4w[j] = Av;
            ars += (double)dot4f(rc, rc);
            apa += (double)dot4f(rc, Av);
            asa += (double)dot4f(Av, Av);
        }
        double v;
        v = block_reduce_d(ars);
        if (threadIdx.x == 0) g_pi[0][blockIdx.x] = v;
        __syncthreads();
        v = block_reduce_d(apa);
        if (threadIdx.x == 0) g_pi[1][blockIdx.x] = v;
        __syncthreads();
        v = block_reduce_d(asa);
        if (threadIdx.x == 0) g_pi[2][blockIdx.x] = v;
    }
    grid_bar();
    double rs  = sum_partials_d(g_pi[0]);
    double pAp = sum_partials_d(g_pi[1]);
    double sAs = sum_partials_d(g_pi[2]);

    // ---- CG alpha-steps: fused pass + 1 barrier each ----
    float alph[NGEN];
    float bet [NGEN];
    int it = 0;
    int npass = 0;
    int scur = 0;

    for (;;) {
        float alpha_f = (float)(rs / (pAp + 1e-300));
        double ad = (double)alpha_f;
        double rs_new = rs - 2.0 * ad * pAp + ad * ad * sAs;
        if (rs_new < 0.0) rs_new = 0.0;
        alph[it] = alpha_f;
        it++;
        if (sqrt(rs_new) < CG_TAU || it >= NGEN) break;   // final a*p in epilogue

        float beta_f = (float)(rs_new / (rs + 1e-300));
        bet[it] = beta_f;
        int par = (npass + 1) & 1;
        double apa, asa;

        const float4* ssrc = (const float4*)(scur ? g_s1 : g_s0);
        float4*       sdst = (float4*)(scur ? g_s0 : g_s1);

        if (npass == 0) {
            fused_pass<true >((const float4*)g_rg[0], ssrc,
                              (float4*)g_rg[1], sdst,
                              p4, D4, alpha_f, beta_f, tid, lane, apa, asa);
        } else {
            fused_pass<false>((const float4*)g_rg[npass], ssrc,
                              (float4*)g_rg[npass + 1], sdst,
                              p4, D4, alpha_f, beta_f, tid, lane, apa, asa);
        }
        {
            double a0 = block_reduce_d(apa);
            __syncthreads();
            double b0 = block_reduce_d(asa);
            if (threadIdx.x == 0) {
                g_pd[par][0][blockIdx.x] = a0;
                g_pd[par][1][blockIdx.x] = b0;
            }
        }
        grid_bar();
        pAp = sum_partials_d(g_pd[par][0]);
        sAs = sum_partials_d(g_pd[par][1]);
        rs  = rs_new;
        npass++;
        scur ^= 1;
    }

    // ---- coefficients: u_tilde = u + sum_{m<it} c_m * r_m ----
    // p_0 = r_0, p_k = r_k + b_k p_{k-1}  =>  c_m = a_m + b_{m+1} c_{m+1}
    float c[NGEN];
    c[it - 1] = alph[it - 1];
    for (int m = it - 2; m >= 0; m--)
        c[m] = fmaf(bet[m + 1], c[m + 1], alph[m]);

    // ---- epilogue: reconstruct u_tilde, ETD rational update, clip ----
    float kk = __ldg(&kp[0]);
    float a  = kk - __ldg(&aCp[0]) * __ldg(&Ctp[0]);
    float bc = kk;                               // k / K_CAP, K_CAP = 1
    float adc = fminf(fmaxf(a * DT_C, -60.0f), 60.0f);
    float e   = expf(adc);
    float em1 = e - 1.0f;

    const float4* __restrict__ u4 = (const float4*)u;
    float4* __restrict__ o4 = (float4*)out;
    const int g = it;

    for (int j = tid; j < N4; j += NTHREADS) {
        float4 ut = __ldg(u4 + j);
        for (int m = 0; m < g; m++) {
            float4 rv = ((const float4*)g_rg[m])[j];
            float cm = c[m];
            ut.x = fmaf(cm, rv.x, ut.x);
            ut.y = fmaf(cm, rv.y, ut.y);
            ut.z = fmaf(cm, rv.z, ut.z);
            ut.w = fmaf(cm, rv.w, ut.w);
        }
        float4 un;
        {
            float num = a * ut.x * e;
            float den = fmaf(bc * ut.x, em1, a);
            un.x = (fabsf(den) > 1e-12f) ? (num / den) : ut.x;
            num = a * ut.y * e;
            den = fmaf(bc * ut.y, em1, a);
            un.y = (fabsf(den) > 1e-12f) ? (num / den) : ut.y;
            num = a * ut.z * e;
            den = fmaf(bc * ut.z, em1, a);
            un.z = (fabsf(den) > 1e-12f) ? (num / den) : ut.z;
            num = a * ut.w * e;
            den = fmaf(bc * ut.w, em1, a);
            un.w = (fabsf(den) > 1e-12f) ? (num / den) : ut.w;
        }
        un.x = fminf(fmaxf(un.x, 0.0f), 1.0f);
        un.y = fminf(fmaxf(un.y, 0.0f), 1.0f);
        un.z = fminf(fmaxf(un.z, 0.0f), 1.0f);
        un.w = fminf(fmaxf(un.w, 0.0f), 1.0f);
        o4[j] = un;
    }
}

// ---------------------------------------------------------------------------

extern "C" void kernel_launch(void* const* d_in, const int* in_sizes, int n_in,
                              void* d_out, int out_size)
{
    const float* u   = (const float*)d_in[0];
    const float* D   = (const float*)d_in[1];
    const float* k   = (const float*)d_in[2];
    const float* aC  = (const float*)d_in[3];
    const float* C_t = (const float*)d_in[4];
    float* out = (float*)d_out;

    imexetd_cg_kernel<<<GBLK, TBLK>>>(u, D, k, aC, C_t, out);
}

// round 10
// speedup vs baseline: 2.0494x; 1.0247x over previous
#include <cuda_runtime.h>

// ---------------------------------------------------------------------------
// IMEX-ETD: CG-solve (I - DT*D*Lap_neumann) x = u, then pointwise ETD update.
// Round 10: SAME algorithm as round 9 (direct dots -> exact 3-step trajectory,
// 7N fused passes, shuffle laterals, u_tilde from saved r generations).
// ONLY change: launch geometry 304 blocks x 512 threads = 2 co-resident
// blocks/SM -> 64 warps/SM (100% occupancy) to hide memory latency.
// ---------------------------------------------------------------------------

#define N_ELEM   8388608     // 8 * 1 * 1024 * 1024
#define N4       2097152     // float4 count
#define ROW4     256         // float4s per row
#define GBLK     304         // 2 blocks per SM x 152 SMs (all co-resident)
#define TBLK     512
#define NWARP    16
#define NTHREADS (GBLK * TBLK)

#define DT_C     0.1f
#define CG_TAU   0.015
#define NGEN     5

__device__ float g_rg[NGEN][N_ELEM];   // r generations (r0..r4)
__device__ float g_s0[N_ELEM];          // Ap ping
__device__ float g_s1[N_ELEM];          // Ap pong
__device__ float g_p [N_ELEM];

__device__ double g_pd[2][2][GBLK];     // pass partials (parity x {pAp,sAs})
__device__ double g_pi[3][GBLK];        // init partials: rs, pAp, sAs

__device__ unsigned g_cnt = 0;
__device__ volatile unsigned g_gen = 0;

// ---------------------------------------------------------------------------

__device__ __forceinline__ void grid_bar() {
    __syncthreads();
    __threadfence();                       // release
    if (threadIdx.x == 0) {
        unsigned snap = g_gen;
        unsigned arrived = atomicAdd(&g_cnt, 1u);
        if (arrived == GBLK - 1) {
            g_cnt = 0;
            __threadfence();
            g_gen = snap + 1u;
        } else {
            while (g_gen == snap) { }
        }
    }
    __syncthreads();
    __threadfence();                       // acquire (CCTL.IVALL): L1 coherent
}

__device__ __forceinline__ double block_reduce_d(double v) {
    __shared__ double sh[NWARP];
    int lane = threadIdx.x & 31;
    int w    = threadIdx.x >> 5;
#pragma unroll
    for (int o = 16; o; o >>= 1) v += __shfl_down_sync(0xffffffffu, v, o);
    if (lane == 0) sh[w] = v;
    __syncthreads();
    if (w == 0) {
        v = (lane < NWARP) ? sh[lane] : 0.0;
#pragma unroll
        for (int o = 16; o; o >>= 1) v += __shfl_down_sync(0xffffffffu, v, o);
    }
    return v;
}

__device__ __forceinline__ double sum_partials_d(const double* a) {
    __shared__ double tot;
    int t = threadIdx.x;
    if (t < 32) {
        double s = 0.0;
#pragma unroll
        for (int j = t; j < GBLK; j += 32) s += a[j];
#pragma unroll
        for (int o = 16; o; o >>= 1) s += __shfl_down_sync(0xffffffffu, s, o);
        if (t == 0) tot = s;
    }
    __syncthreads();
    return tot;
}

// ---------------------------------------------------------------------------

__device__ __forceinline__ float dot4f(float4 a, float4 b) {
    return fmaf(a.x, b.x, fmaf(a.y, b.y, fmaf(a.z, b.z, a.w * b.w)));
}

__device__ __forceinline__ float4 lap_mk(float4 c, float4 t, float4 b,
                                         float lf, float rt) {
    float4 L;
    L.x = fmaf(-4.0f, c.x, (lf  + c.y) + (t.x + b.x));
    L.y = fmaf(-4.0f, c.y, (c.x + c.z) + (t.y + b.y));
    L.z = fmaf(-4.0f, c.z, (c.y + c.w) + (t.z + b.z));
    L.w = fmaf(-4.0f, c.w, (c.z + rt ) + (t.w + b.w));
    return L;
}

// r0 = DT * D * lap(u) at float4 index j
__device__ __forceinline__ float4 r0_vec(const float* __restrict__ u,
                                         const float* __restrict__ D, int j) {
    int x4 = j & (ROW4 - 1);
    int y  = (j >> 8) & 1023;
    const float4* u4 = (const float4*)u;
    float4 c = __ldg(u4 + j);
    float4 t = (y > 0)    ? __ldg(u4 + (j - ROW4)) : c;
    float4 b = (y < 1023) ? __ldg(u4 + (j + ROW4)) : c;
    float lf = (x4 > 0)        ? __ldg(u + 4*j - 1) : c.x;
    float rt = (x4 < ROW4 - 1) ? __ldg(u + 4*j + 4) : c.w;
    float4 dd = __ldg(((const float4*)D) + j);
    float4 lp = lap_mk(c, t, b, lf, rt);
    float4 rv;
    rv.x = DT_C * dd.x * lp.x;
    rv.y = DT_C * dd.y * lp.y;
    rv.z = DT_C * dd.z * lp.z;
    rv.w = DT_C * dd.w * lp.w;
    return rv;
}

__device__ __forceinline__ float r0_scalar(const float* __restrict__ u,
                                           const float* __restrict__ D, int i) {
    int x = i & 1023;
    int y = (i >> 10) & 1023;
    float c = __ldg(&u[i]);
    float l = (x > 0)    ? __ldg(&u[i - 1])    : c;
    float r = (x < 1023) ? __ldg(&u[i + 1])    : c;
    float t = (y > 0)    ? __ldg(&u[i - 1024]) : c;
    float b = (y < 1023) ? __ldg(&u[i + 1024]) : c;
    return DT_C * __ldg(&D[i]) * fmaf(-4.0f, c, (l + r) + (t + b));
}

// ---------------------------------------------------------------------------
// Fused CG pass, 7N traffic. Lateral neighbors via warp shuffle (warp-uniform
// loop; each warp covers 32 contiguous float4s of one row). Dots (pn,sn) and
// (sn,sn) measured DIRECTLY (valid for non-symmetric A).

template <bool FIRST>
__device__ __forceinline__ void fused_pass(
    const float4* __restrict__ rsrc4,
    const float4* __restrict__ ssrc4,
    float4*       __restrict__ rdst4,
    float4*       __restrict__ sdst4,
    float4*       __restrict__ p4,
    const float4* __restrict__ D4,
    float alpha_f, float beta_f,
    int tid, int lane, double& apa_out, double& asa_out)
{
    const float* __restrict__ rs_f = (const float*)rsrc4;
    const float* __restrict__ ss_f = (const float*)ssrc4;
    double apa = 0.0, asa = 0.0;

    for (int j = tid; j < N4; j += NTHREADS) {
        int x4 = j & (ROW4 - 1);
        int y  = (j >> 8) & 1023;
        bool hT = (y > 0), hB = (y < 1023);

        float4 rc = rsrc4[j];
        float4 sc = ssrc4[j];
        float4 rT = hT ? rsrc4[j - ROW4] : rc;
        float4 rB = hB ? rsrc4[j + ROW4] : rc;
        float4 sT = hT ? ssrc4[j - ROW4] : sc;
        float4 sB = hB ? ssrc4[j + ROW4] : sc;

        // lateral neighbors: shuffle; warp-edge lanes hit gmem
        float rL = __shfl_up_sync(0xffffffffu, rc.w, 1);
        float sL = __shfl_up_sync(0xffffffffu, sc.w, 1);
        float rR = __shfl_down_sync(0xffffffffu, rc.x, 1);
        float sR = __shfl_down_sync(0xffffffffu, sc.x, 1);
        if (lane == 0) {
            rL = (x4 > 0) ? rs_f[4*j - 1] : rc.x;
            sL = (x4 > 0) ? ss_f[4*j - 1] : sc.x;
        }
        if (lane == 31) {
            rR = (x4 < ROW4 - 1) ? rs_f[4*j + 4] : rc.w;
            sR = (x4 < ROW4 - 1) ? ss_f[4*j + 4] : sc.w;
        }

        float4 dd = __ldg(D4 + j);
        float4 pv = FIRST ? rc : p4[j];

        float4 lr = lap_mk(rc, rT, rB, rL, rR);
        float4 ls = lap_mk(sc, sT, sB, sL, sR);

        // r_new = r - a*s
        float4 rn;
        rn.x = fmaf(-alpha_f, sc.x, rc.x);
        rn.y = fmaf(-alpha_f, sc.y, rc.y);
        rn.z = fmaf(-alpha_f, sc.z, rc.z);
        rn.w = fmaf(-alpha_f, sc.w, rc.w);

        // w = A r_new = r_new - DT*D*(lap r - a*lap s)
        float4 w;
        {
            float lx = fmaf(-alpha_f, ls.x, lr.x);
            float ly = fmaf(-alpha_f, ls.y, lr.y);
            float lz = fmaf(-alpha_f, ls.z, lr.z);
            float lw = fmaf(-alpha_f, ls.w, lr.w);
            w.x = fmaf(-DT_C * dd.x, lx, rn.x);
            w.y = fmaf(-DT_C * dd.y, ly, rn.y);
            w.z = fmaf(-DT_C * dd.z, lz, rn.z);
            w.w = fmaf(-DT_C * dd.w, lw, rn.w);
        }

        // p_new = r_new + b*p ; s_new = w + b*s
        float4 pn, sn;
        pn.x = fmaf(beta_f, pv.x, rn.x);
        pn.y = fmaf(beta_f, pv.y, rn.y);
        pn.z = fmaf(beta_f, pv.z, rn.z);
        pn.w = fmaf(beta_f, pv.w, rn.w);
        sn.x = fmaf(beta_f, sc.x, w.x);
        sn.y = fmaf(beta_f, sc.y, w.y);
        sn.z = fmaf(beta_f, sc.z, w.z);
        sn.w = fmaf(beta_f, sc.w, w.w);

        rdst4[j] = rn;
        sdst4[j] = sn;
        p4[j]    = pn;

        apa += (double)dot4f(pn, sn);
        asa += (double)dot4f(sn, sn);
    }
    apa_out = apa;
    asa_out = asa;
}

// ---------------------------------------------------------------------------

__global__ void __launch_bounds__(TBLK, 2)
imexetd_cg_kernel(const float* __restrict__ u,
                  const float* __restrict__ D,
                  const float* __restrict__ kp,
                  const float* __restrict__ aCp,
                  const float* __restrict__ Ctp,
                  float* __restrict__ out)
{
    const int tid  = blockIdx.x * TBLK + threadIdx.x;
    const int lane = threadIdx.x & 31;
    const float4* D4 = (const float4*)D;
    float4* p4 = (float4*)g_p;

    // ---- fused init: r0 = DT*D*lap(u); s0 = A r0; dots rs, pAp, sAs ----
    {
        float4* __restrict__ r4w = (float4*)g_rg[0];
        float4* __restrict__ s4w = (float4*)g_s0;
        double ars = 0.0, apa = 0.0, asa = 0.0;
        for (int j = tid; j < N4; j += NTHREADS) {
            int x4 = j & (ROW4 - 1);
            int y  = (j >> 8) & 1023;
            float4 rc = r0_vec(u, D, j);
            float4 rT = (y > 0)    ? r0_vec(u, D, j - ROW4) : rc;
            float4 rB = (y < 1023) ? r0_vec(u, D, j + ROW4) : rc;
            float rL = __shfl_up_sync(0xffffffffu, rc.w, 1);
            float rR = __shfl_down_sync(0xffffffffu, rc.x, 1);
            if (lane == 0)
                rL = (x4 > 0) ? r0_scalar(u, D, 4*j - 1) : rc.x;
            if (lane == 31)
                rR = (x4 < ROW4 - 1) ? r0_scalar(u, D, 4*j + 4) : rc.w;
            float4 dd = __ldg(D4 + j);
            float4 lp = lap_mk(rc, rT, rB, rL, rR);
            float4 Av;
            Av.x = fmaf(-DT_C * dd.x, lp.x, rc.x);
            Av.y = fmaf(-DT_C * dd.y, lp.y, rc.y);
            Av.z = fmaf(-DT_C * dd.z, lp.z, rc.z);
            Av.w = fmaf(-DT_C * dd.w, lp.w, rc.w);
            r4w[j] = rc;
            s4w[j] = Av;
            ars += (double)dot4f(rc, rc);
            apa += (double)dot4f(rc, Av);
            asa += (double)dot4f(Av, Av);
        }
        double v;
        v = block_reduce_d(ars);
        if (threadIdx.x == 0) g_pi[0][blockIdx.x] = v;
        __syncthreads();
        v = block_reduce_d(apa);
        if (threadIdx.x == 0) g_pi[1][blockIdx.x] = v;
        __syncthreads();
        v = block_reduce_d(asa);
        if (threadIdx.x == 0) g_pi[2][blockIdx.x] = v;
    }
    grid_bar();
    double rs  = sum_partials_d(g_pi[0]);
    double pAp = sum_partials_d(g_pi[1]);
    double sAs = sum_partials_d(g_pi[2]);

    // ---- CG alpha-steps: fused pass + 1 barrier each ----
    float alph[NGEN];
    float bet [NGEN];
    int it = 0;
    int npass = 0;
    int scur = 0;

    for (;;) {
        float alpha_f = (float)(rs / (pAp + 1e-300));
        double ad = (double)alpha_f;
        double rs_new = rs - 2.0 * ad * pAp + ad * ad * sAs;
        if (rs_new < 0.0) rs_new = 0.0;
        alph[it] = alpha_f;
        it++;
        if (sqrt(rs_new) < CG_TAU || it >= NGEN) break;   // final a*p in epilogue

        float beta_f = (float)(rs_new / (rs + 1e-300));
        bet[it] = beta_f;
        int par = (npass + 1) & 1;
        double apa, asa;

        const float4* ssrc = (const float4*)(scur ? g_s1 : g_s0);
        float4*       sdst = (float4*)(scur ? g_s0 : g_s1);

        if (npass == 0) {
            fused_pass<true >((const float4*)g_rg[0], ssrc,
                              (float4*)g_rg[1], sdst,
                              p4, D4, alpha_f, beta_f, tid, lane, apa, asa);
        } else {
            fused_pass<false>((const float4*)g_rg[npass], ssrc,
                              (float4*)g_rg[npass + 1], sdst,
                              p4, D4, alpha_f, beta_f, tid, lane, apa, asa);
        }
        {
            double a0 = block_reduce_d(apa);
            __syncthreads();
            double b0 = block_reduce_d(asa);
            if (threadIdx.x == 0) {
                g_pd[par][0][blockIdx.x] = a0;
                g_pd[par][1][blockIdx.x] = b0;
            }
        }
        grid_bar();
        pAp = sum_partials_d(g_pd[par][0]);
        sAs = sum_partials_d(g_pd[par][1]);
        rs  = rs_new;
        npass++;
        scur ^= 1;
    }

    // ---- coefficients: u_tilde = u + sum_{m<it} c_m * r_m ----
    float c[NGEN];
    c[it - 1] = alph[it - 1];
    for (int m = it - 2; m >= 0; m--)
        c[m] = fmaf(bet[m + 1], c[m + 1], alph[m]);

    // ---- epilogue: reconstruct u_tilde, ETD rational update, clip ----
    float kk = __ldg(&kp[0]);
    float a  = kk - __ldg(&aCp[0]) * __ldg(&Ctp[0]);
    float bc = kk;                               // k / K_CAP, K_CAP = 1
    float adc = fminf(fmaxf(a * DT_C, -60.0f), 60.0f);
    float e   = expf(adc);
    float em1 = e - 1.0f;

    const float4* __restrict__ u4 = (const float4*)u;
    float4* __restrict__ o4 = (float4*)out;
    const int g = it;

    for (int j = tid; j < N4; j += NTHREADS) {
        float4 ut = __ldg(u4 + j);
        for (int m = 0; m < g; m++) {
            float4 rv = ((const float4*)g_rg[m])[j];
            float cm = c[m];
            ut.x = fmaf(cm, rv.x, ut.x);
            ut.y = fmaf(cm, rv.y, ut.y);
            ut.z = fmaf(cm, rv.z, ut.z);
            ut.w = fmaf(cm, rv.w, ut.w);
        }
        float4 un;
        {
            float num = a * ut.x * e;
            float den = fmaf(bc * ut.x, em1, a);
            un.x = (fabsf(den) > 1e-12f) ? (num / den) : ut.x;
            num = a * ut.y * e;
            den = fmaf(bc * ut.y, em1, a);
            un.y = (fabsf(den) > 1e-12f) ? (num / den) : ut.y;
            num = a * ut.z * e;
            den = fmaf(bc * ut.z, em1, a);
            un.z = (fabsf(den) > 1e-12f) ? (num / den) : ut.z;
            num = a * ut.w * e;
            den = fmaf(bc * ut.w, em1, a);
            un.w = (fabsf(den) > 1e-12f) ? (num / den) : ut.w;
        }
        un.x = fminf(fmaxf(un.x, 0.0f), 1.0f);
        un.y = fminf(fmaxf(un.y, 0.0f), 1.0f);
        un.z = fminf(fmaxf(un.z, 0.0f), 1.0f);
        un.w = fminf(fmaxf(un.w, 0.0f), 1.0f);
        o4[j] = un;
    }
}

// ---------------------------------------------------------------------------

extern "C" void kernel_launch(void* const* d_in, const int* in_sizes, int n_in,
                              void* d_out, int out_size)
{
    const float* u   = (const float*)d_in[0];
    const float* D   = (const float*)d_in[1];
    const float* k   = (const float*)d_in[2];
    const float* aC  = (const float*)d_in[3];
    const float* C_t = (const float*)d_in[4];
    float* out = (float*)d_out;

    imexetd_cg_kernel<<<GBLK, TBLK>>>(u, D, k, aC, C_t, out);
}